// round 15
// baseline (speedup 1.0000x reference)
#include <cuda_runtime.h>
#include <cuda_fp16.h>
#include <cstdint>

// ---------------------------------------------------------------------------
// CorrBlock: pooled-fmap2 fp16 HMMA GEMM (1-pass: Ahi*Bhi) + warp sampler.
// Round 15: GEMM grid.x 44 -> 43 (tile 43 was 100% waste: 43*128=5504>=5440);
//           prep f1-convert MLP 2 -> 4 float4/thread.
// All other stages frozen (measured optima: GEMM 73us, sampler 54us).
// ---------------------------------------------------------------------------

#define Bb 2
#define Cc 256
#define HH 64
#define WW 64
#define NN 8
#define QTOT 5440
#define QPAD 5632      // stride; pad region = don't-care
#define PTOT 4096      // H*W
#define NTILES 43      // ceil(5440/128); tile 43 would be entirely q>=5504 waste

// Scratch (no cudaMalloc allowed)
__device__ __half g_Bt[(size_t)Bb * Cc * QPAD];           // 5.8 MB [b][c][QPAD] fp16
__device__ __half g_Ah[(size_t)Bb * Cc * PTOT];           // 4.2 MB [b][c][m] fp16
__device__ __half g_corrh[(size_t)Bb * PTOT * QTOT];      // 89 MB  fp16 corr

__device__ __forceinline__ uint32_t smem_to_u32(const void* p) {
    uint32_t a;
    asm("{ .reg .u64 t; cvta.to.shared.u64 t, %1; cvt.u32.u64 %0, t; }" : "=r"(a) : "l"(p));
    return a;
}
__device__ __forceinline__ void cp_async16(uint32_t dst, const void* src) {
    asm volatile("cp.async.cg.shared.global [%0], [%1], 16;" :: "r"(dst), "l"(src));
}
__device__ __forceinline__ void ldsm_x4_trans(uint32_t* r, uint32_t addr) {
    asm volatile("ldmatrix.sync.aligned.m8n8.x4.trans.shared.b16 {%0,%1,%2,%3}, [%4];"
                 : "=r"(r[0]), "=r"(r[1]), "=r"(r[2]), "=r"(r[3]) : "r"(addr));
}
__device__ __forceinline__ void mma16816(float* d, const uint32_t* a, uint32_t b0, uint32_t b1) {
    asm volatile("mma.sync.aligned.m16n8k16.row.col.f32.f16.f16.f32 "
                 "{%0,%1,%2,%3}, {%4,%5,%6,%7}, {%8,%9}, {%0,%1,%2,%3};"
                 : "+f"(d[0]), "+f"(d[1]), "+f"(d[2]), "+f"(d[3])
                 : "r"(a[0]), "r"(a[1]), "r"(a[2]), "r"(a[3]), "r"(b0), "r"(b1));
}

// ---------------------------------------------------------------------------
// Kernel 1: fused prep. Blocks [0,512): pool fmap2 -> fp16 g_Bt.
//           Blocks [512,1024): fp32->fp16 copy of f1 (4 float4/thread).
// ---------------------------------------------------------------------------
__global__ __launch_bounds__(256) void prep_kernel(const float* __restrict__ f2,
                                                   const float* __restrict__ f1) {
    __shared__ float s0[4096];
    __shared__ float s1[1024];
    __shared__ float s2[256];
    const int blk = blockIdx.x;
    const int tid = threadIdx.x;

    if (blk < 512) {
        int c = blk & 255, b = blk >> 8;
        const float* in = f2 + ((size_t)b * Cc + c) * (HH * WW);
        __half* outp = g_Bt + ((size_t)b * Cc + c) * QPAD;
        for (int i = tid; i < 1024; i += 256) {
            float4 v = ((const float4*)in)[i];
            ((float4*)s0)[i] = v;
            ((__half2*)outp)[2 * i]     = __floats2half2_rn(v.x, v.y);
            ((__half2*)outp)[2 * i + 1] = __floats2half2_rn(v.z, v.w);
        }
        __syncthreads();
        for (int o = tid; o < 1024; o += 256) {
            int y = o >> 5, x = o & 31;
            float v = 0.25f * (s0[(2*y)*64 + 2*x] + s0[(2*y)*64 + 2*x + 1]
                             + s0[(2*y+1)*64 + 2*x] + s0[(2*y+1)*64 + 2*x + 1]);
            s1[o] = v; outp[4096 + o] = __float2half_rn(v);
        }
        __syncthreads();
        {
            int y = tid >> 4, x = tid & 15;
            float v = 0.25f * (s1[(2*y)*32 + 2*x] + s1[(2*y)*32 + 2*x + 1]
                             + s1[(2*y+1)*32 + 2*x] + s1[(2*y+1)*32 + 2*x + 1]);
            s2[tid] = v; outp[5120 + tid] = __float2half_rn(v);
        }
        __syncthreads();
        if (tid < 64) {
            int y = tid >> 3, x = tid & 7;
            float v = 0.25f * (s2[(2*y)*16 + 2*x] + s2[(2*y)*16 + 2*x + 1]
                             + s2[(2*y+1)*16 + 2*x] + s2[(2*y+1)*16 + 2*x + 1]);
            outp[5376 + tid] = __float2half_rn(v);
        }
    } else {
        // fp32->fp16 convert of f1, 4 independent float4 loads per thread
        int blk2 = blk - 512;                         // 0..511
        size_t base = (size_t)blk2 * 1024 + tid * 4;  // float4 units (total 524288)
        float4 v0 = ((const float4*)f1)[base];
        float4 v1 = ((const float4*)f1)[base + 1];
        float4 v2 = ((const float4*)f1)[base + 2];
        float4 v3 = ((const float4*)f1)[base + 3];
        __half2* o = (__half2*)g_Ah + base * 2;
        o[0] = __floats2half2_rn(v0.x, v0.y); o[1] = __floats2half2_rn(v0.z, v0.w);
        o[2] = __floats2half2_rn(v1.x, v1.y); o[3] = __floats2half2_rn(v1.z, v1.w);
        o[4] = __floats2half2_rn(v2.x, v2.y); o[5] = __floats2half2_rn(v2.z, v2.w);
        o[6] = __floats2half2_rn(v3.x, v3.y); o[7] = __floats2half2_rn(v3.z, v3.w);
    }
}

// ---------------------------------------------------------------------------
// Kernel 2: HMMA GEMM (round-13 core). CTA 128x128, BK=64, 4 chunks,
// 256 thr / 8 warps (32x64), 3-stage cp.async, 2 CTAs/SM, trans-ldsm operands.
// grid (43, 32, 2).
// ---------------------------------------------------------------------------
#define GT 256
static constexpr int A_BYTES = 64 * 256;         // 16 KB  [k][m]
static constexpr int B_BYTES = 64 * 256;         // 16 KB  [k][n]
static constexpr int BUF_B = A_BYTES + B_BYTES;  // 32 KB
static constexpr int GEMM_SMEM = 3 * BUF_B;      // 96 KB
#define SWZ256(o) ((o) ^ ((((o) >> 8) & 7) << 4))

__global__ __launch_bounds__(GT, 2) void gemm_kernel() {
    extern __shared__ char smem[];
    const uint32_t sb = smem_to_u32(smem);
    const int tid = threadIdx.x, wid = tid >> 5, lid = tid & 31;
    const int b = blockIdx.z, m0 = blockIdx.y * 128, n0 = blockIdx.x * 128;
    const int warp_m = wid & 3, warp_n = wid >> 2;

    const __half* Ap = g_Ah + (size_t)b * Cc * PTOT;
    const __half* Bp = g_Bt + (size_t)b * Cc * QPAD;

    float acc[2][8][4];
#pragma unroll
    for (int i = 0; i < 2; i++)
#pragma unroll
        for (int j = 0; j < 8; j++)
#pragma unroll
            for (int k = 0; k < 4; k++) acc[i][j][k] = 0.f;

    auto issue_loads = [&](int c, int buf) {
        int k_off = c * 64;
        uint32_t aB = sb + buf * BUF_B;
        uint32_t bB = aB + A_BYTES;
#pragma unroll
        for (int i = 0; i < 8; i++) {
            int idx = tid + i * GT;
            bool isB = idx >= 1024;
            int j = isB ? idx - 1024 : idx;
            int row = j >> 4, u = j & 15;
            const __half* src = isB
                ? Bp + (size_t)(k_off + row) * QPAD + n0 + u * 8
                : Ap + (size_t)(k_off + row) * PTOT + m0 + u * 8;
            uint32_t dst = (isB ? bB : aB) + row * 256 + ((u ^ (row & 7)) << 4);
            cp_async16(dst, src);
        }
        asm volatile("cp.async.commit_group;" ::: "memory");
    };

    issue_loads(0, 0);
    issue_loads(1, 1);

    const int krowA = ((lid >> 4) & 1) * 8 + (lid & 7);
    const int mbyteA = ((lid >> 3) & 1) * 16;
    const int krowB = ((lid >> 3) & 1) * 8 + (lid & 7);
    const int nbyteB = ((lid >> 4) & 1) * 16;

    for (int c = 0; c < 4; c++) {
        if (c < 3) asm volatile("cp.async.wait_group 1;" ::: "memory");
        else       asm volatile("cp.async.wait_group 0;" ::: "memory");
        __syncthreads();
        if (c < 2) issue_loads(c + 2, (c + 2) % 3);

        uint32_t aB = sb + (c % 3) * BUF_B;
        uint32_t bB = aB + A_BYTES;

#pragma unroll
        for (int ks = 0; ks < 4; ks++) {
            uint32_t af[2][4];
#pragma unroll
            for (int mb = 0; mb < 2; mb++) {
                uint32_t off = (uint32_t)((ks * 16 + krowA) * 256
                                          + warp_m * 64 + mb * 32 + mbyteA);
                ldsm_x4_trans(af[mb], aB + SWZ256(off));
            }
            uint32_t bf[4][4];
#pragma unroll
            for (int p = 0; p < 4; p++) {
                uint32_t off = (uint32_t)((ks * 16 + krowB) * 256
                                          + warp_n * 128 + p * 32 + nbyteB);
                ldsm_x4_trans(bf[p], bB + SWZ256(off));
            }
#pragma unroll
            for (int mb = 0; mb < 2; mb++)
#pragma unroll
                for (int nb = 0; nb < 8; nb++)
                    mma16816(acc[mb][nb], af[mb],
                             bf[nb >> 1][(nb & 1) * 2], bf[nb >> 1][(nb & 1) * 2 + 1]);
        }
    }

    const float scale = 0.0625f;
    const int rbase = m0 + warp_m * 32 + (lid >> 2);
    const int cbase = n0 + warp_n * 64 + (lid & 3) * 2;
#pragma unroll
    for (int mb = 0; mb < 2; mb++) {
#pragma unroll
        for (int nb = 0; nb < 8; nb++) {
            int q = cbase + nb * 8;
            if (q < QTOT) {
                int r0 = rbase + mb * 16;
                __half* c0p = g_corrh + ((size_t)b * PTOT + r0) * QTOT + q;
                __half* c1p = c0p + (size_t)8 * QTOT;
                *(__half2*)c0p = __floats2half2_rn(acc[mb][nb][0] * scale,
                                                   acc[mb][nb][1] * scale);
                *(__half2*)c1p = __floats2half2_rn(acc[mb][nb][2] * scale,
                                                   acc[mb][nb][3] * scale);
            }
        }
    }
}

// ---------------------------------------------------------------------------
// Kernel 3: sampler (round-14, unchanged). 256-thr block = 8 n-heads of one
// (b,h,w); overlapping half2 pairs; separable metadata. grid 8192.
// ---------------------------------------------------------------------------
#define PPITCH 20   // half2 units per pair row (80 B)
__global__ __launch_bounds__(256) void sample_kernel(const float* __restrict__ coords,
                                                     float* __restrict__ out) {
    const int warp = threadIdx.x >> 5;
    const int lane = threadIdx.x & 31;
    const int bhw = blockIdx.x;
    const int b = bhw >> 12;
    const int hw = bhw & 4095;
    const int h = hw >> 6;
    const int w = hw & 63;
    const int n = warp;
    const int qid = ((b * NN + n) << 12) | hw;

    __shared__ uint32_t pairs[8][4][10][PPITCH];
    __shared__ float2 xdat[8][4][9];
    __shared__ float2 ydat[8][4][9];

    const float cx = coords[((((size_t)b * NN + n) * 2 + 0) * HH + h) * WW + w];
    const float cy = coords[((((size_t)b * NN + n) * 2 + 1) * HH + h) * WW + w];

    const __half* corrRow = g_corrh + ((size_t)b * PTOT + hw) * QTOT;
    float* outBase = out + (size_t)qid * 324;

    const int   lvl_off[4] = {0, 4096, 5120, 5376};
    const int   wl[4]      = {64, 32, 16, 8};
    const float inv[4]     = {1.f, 0.5f, 0.25f, 0.125f};

#pragma unroll
    for (int lvl = 0; lvl < 4; lvl++) {
        const int   w2  = wl[lvl];
        const float wm1 = (float)(w2 - 1);
        const float cxs = cx * inv[lvl];
        const float cys = cy * inv[lvl];
        const float ylo = fminf(fmaxf(cys - 4.f, 0.f), wm1);
        const float yhi = fminf(fmaxf(cys + 4.f, 0.f), wm1);
        const float xlo = fminf(fmaxf(cxs - 4.f, 0.f), wm1);
        const int xstart = (int)floorf(xlo);
        const int ystart = (int)floorf(ylo);
        const int yend   = min((int)floorf(yhi) + 1, w2 - 1);
        const int xs4    = xstart & ~3;

        const __half* lbase = corrRow + lvl_off[lvl];
#pragma unroll
        for (int s = 0; s < 2; s++) {
            int slot = lane + s * 32;
            int r = slot >> 2, cb = slot & 3;
            int col = xs4 + cb * 4;
            uint2 v = make_uint2(0u, 0u);
            if (slot < 40 && r <= yend - ystart && col < w2)
                v = *(const uint2*)(lbase + (ystart + r) * w2 + col);
            uint32_t nxt = __shfl_down_sync(0xffffffffu, v.x, 1);
            uint32_t p0 = v.x;
            uint32_t p1 = (v.x >> 16) | (v.y << 16);
            uint32_t p2 = v.y;
            uint32_t p3 = (v.y >> 16) | (nxt << 16);
            if (slot < 40)
                *(uint4*)&pairs[warp][lvl][r][cb * 4] = make_uint4(p0, p1, p2, p3);
        }
        {
            int grp = lane >> 4;
            int off = lane & 15;
            if (off < 9 && grp < 2) {
                float c   = grp ? cys : cxs;
                int   sub = grp ? ystart : xs4;
                int   str = grp ? (PPITCH * 4) : 4;
                int   bas = grp ? (warp * 4 + lvl) * (10 * PPITCH * 4) : 0;
                float v   = fminf(fmaxf(c + (float)(off - 4), 0.f), wm1);
                float v0f = floorf(v);
                float f   = v - v0f;
                int   i0  = (int)v0f;
                uint32_t packed;
                if (grp) {
                    int i1 = min(i0 + 1, w2 - 1);
                    packed = (uint32_t)(bas + (i0 - sub) * str)
                           | ((uint32_t)(bas + (i1 - sub) * str) << 16);
                } else {
                    packed = (uint32_t)((i0 - sub) * str);
                }
                float2 md = make_float2(f, __uint_as_float(packed));
                if (grp) ydat[warp][lvl][off] = md;
                else     xdat[warp][lvl][off] = md;
            }
        }
    }
    __syncwarp();

    const char* pbase = (const char*)&pairs[0][0][0][0];
#pragma unroll
    for (int s = 0; s < 3; s++) {
        int t = lane + s * 32;
        if (t < 81) {
            int ix = t / 9;
            int iy = t - ix * 9;
#pragma unroll
            for (int lvl = 0; lvl < 4; lvl++) {
                float2 xd = xdat[warp][lvl][ix];
                float2 yd = ydat[warp][lvl][iy];
                uint32_t xo = __float_as_uint(xd.y);
                uint32_t yp = __float_as_uint(yd.y);
                uint32_t pa = *(const uint32_t*)(pbase + (yp & 0xFFFFu) + xo);
                uint32_t pc = *(const uint32_t*)(pbase + (yp >> 16) + xo);
                float2 a = __half22float2(*(__half2*)&pa);
                float2 c2 = __half22float2(*(__half2*)&pc);
                float h0 = fmaf(xd.x, a.y - a.x, a.x);
                float h1 = fmaf(xd.x, c2.y - c2.x, c2.x);
                outBase[lvl * 81 + t] = fmaf(yd.x, h1 - h0, h0);
            }
        }
    }
}

// ---------------------------------------------------------------------------
// Launch
// ---------------------------------------------------------------------------
extern "C" void kernel_launch(void* const* d_in, const int* in_sizes, int n_in,
                              void* d_out, int out_size) {
    const float* f1     = (const float*)d_in[0];
    const float* f2     = (const float*)d_in[1];
    const float* coords = (const float*)d_in[2];
    float* out          = (float*)d_out;

    prep_kernel<<<512 + 512, 256>>>(f2, f1);

    cudaFuncSetAttribute(gemm_kernel, cudaFuncAttributeMaxDynamicSharedMemorySize, GEMM_SMEM);
    gemm_kernel<<<dim3(NTILES, PTOT / 128, Bb), GT, GEMM_SMEM>>>();

    sample_kernel<<<Bb * HH * WW, 256>>>(coords, out);
}

// round 16
// speedup vs baseline: 1.0153x; 1.0153x over previous
#include <cuda_runtime.h>
#include <cuda_fp16.h>
#include <cstdint>

// ---------------------------------------------------------------------------
// CorrBlock: pooled-fmap2 fp16 HMMA GEMM (1-pass: Ahi*Bhi) + warp sampler.
// Round 16: prep reverted to round-14 shape (1536 blocks, 2 float4/thread —
//           measured 8.3us; round-15's 1024-block variant regressed to 10.9);
//           GEMM keeps NTILES=43 (tile 43 was 100% waste).
// ---------------------------------------------------------------------------

#define Bb 2
#define Cc 256
#define HH 64
#define WW 64
#define NN 8
#define QTOT 5440
#define QPAD 5632      // stride; pad region = don't-care
#define PTOT 4096      // H*W
#define NTILES 43      // ceil(5440/128); 44th tile entirely q>=5504 waste

// Scratch (no cudaMalloc allowed)
__device__ __half g_Bt[(size_t)Bb * Cc * QPAD];           // 5.8 MB [b][c][QPAD] fp16
__device__ __half g_Ah[(size_t)Bb * Cc * PTOT];           // 4.2 MB [b][c][m] fp16
__device__ __half g_corrh[(size_t)Bb * PTOT * QTOT];      // 89 MB  fp16 corr

__device__ __forceinline__ uint32_t smem_to_u32(const void* p) {
    uint32_t a;
    asm("{ .reg .u64 t; cvta.to.shared.u64 t, %1; cvt.u32.u64 %0, t; }" : "=r"(a) : "l"(p));
    return a;
}
__device__ __forceinline__ void cp_async16(uint32_t dst, const void* src) {
    asm volatile("cp.async.cg.shared.global [%0], [%1], 16;" :: "r"(dst), "l"(src));
}
__device__ __forceinline__ void ldsm_x4_trans(uint32_t* r, uint32_t addr) {
    asm volatile("ldmatrix.sync.aligned.m8n8.x4.trans.shared.b16 {%0,%1,%2,%3}, [%4];"
                 : "=r"(r[0]), "=r"(r[1]), "=r"(r[2]), "=r"(r[3]) : "r"(addr));
}
__device__ __forceinline__ void mma16816(float* d, const uint32_t* a, uint32_t b0, uint32_t b1) {
    asm volatile("mma.sync.aligned.m16n8k16.row.col.f32.f16.f16.f32 "
                 "{%0,%1,%2,%3}, {%4,%5,%6,%7}, {%8,%9}, {%0,%1,%2,%3};"
                 : "+f"(d[0]), "+f"(d[1]), "+f"(d[2]), "+f"(d[3])
                 : "r"(a[0]), "r"(a[1]), "r"(a[2]), "r"(a[3]), "r"(b0), "r"(b1));
}

// ---------------------------------------------------------------------------
// Kernel 1: fused prep (round-14 shape). Blocks [0,512): pool fmap2 -> g_Bt.
//           Blocks [512,1536): fp32->fp16 copy of f1 (2 float4/thread).
// ---------------------------------------------------------------------------
__global__ __launch_bounds__(256) void prep_kernel(const float* __restrict__ f2,
                                                   const float* __restrict__ f1) {
    __shared__ float s0[4096];
    __shared__ float s1[1024];
    __shared__ float s2[256];
    const int blk = blockIdx.x;
    const int tid = threadIdx.x;

    if (blk < 512) {
        int c = blk & 255, b = blk >> 8;
        const float* in = f2 + ((size_t)b * Cc + c) * (HH * WW);
        __half* outp = g_Bt + ((size_t)b * Cc + c) * QPAD;
        for (int i = tid; i < 1024; i += 256) {
            float4 v = ((const float4*)in)[i];
            ((float4*)s0)[i] = v;
            ((__half2*)outp)[2 * i]     = __floats2half2_rn(v.x, v.y);
            ((__half2*)outp)[2 * i + 1] = __floats2half2_rn(v.z, v.w);
        }
        __syncthreads();
        for (int o = tid; o < 1024; o += 256) {
            int y = o >> 5, x = o & 31;
            float v = 0.25f * (s0[(2*y)*64 + 2*x] + s0[(2*y)*64 + 2*x + 1]
                             + s0[(2*y+1)*64 + 2*x] + s0[(2*y+1)*64 + 2*x + 1]);
            s1[o] = v; outp[4096 + o] = __float2half_rn(v);
        }
        __syncthreads();
        {
            int y = tid >> 4, x = tid & 15;
            float v = 0.25f * (s1[(2*y)*32 + 2*x] + s1[(2*y)*32 + 2*x + 1]
                             + s1[(2*y+1)*32 + 2*x] + s1[(2*y+1)*32 + 2*x + 1]);
            s2[tid] = v; outp[5120 + tid] = __float2half_rn(v);
        }
        __syncthreads();
        if (tid < 64) {
            int y = tid >> 3, x = tid & 7;
            float v = 0.25f * (s2[(2*y)*16 + 2*x] + s2[(2*y)*16 + 2*x + 1]
                             + s2[(2*y+1)*16 + 2*x] + s2[(2*y+1)*16 + 2*x + 1]);
            outp[5376 + tid] = __float2half_rn(v);
        }
    } else {
        int blk2 = blk - 512;                    // 0..1023
        size_t base = (size_t)blk2 * 512 + tid * 2;   // float4 units (total 524288)
#pragma unroll
        for (int i = 0; i < 2; i++) {
            float4 v = ((const float4*)f1)[base + i];
            ((__half2*)g_Ah)[(base + i) * 2]     = __floats2half2_rn(v.x, v.y);
            ((__half2*)g_Ah)[(base + i) * 2 + 1] = __floats2half2_rn(v.z, v.w);
        }
    }
}

// ---------------------------------------------------------------------------
// Kernel 2: HMMA GEMM. CTA 128x128, BK=64, 4 chunks, 256 thr / 8 warps (32x64),
// 3-stage cp.async, 2 CTAs/SM, trans-ldsm operands. grid (43, 32, 2).
// ---------------------------------------------------------------------------
#define GT 256
static constexpr int A_BYTES = 64 * 256;         // 16 KB  [k][m]
static constexpr int B_BYTES = 64 * 256;         // 16 KB  [k][n]
static constexpr int BUF_B = A_BYTES + B_BYTES;  // 32 KB
static constexpr int GEMM_SMEM = 3 * BUF_B;      // 96 KB
#define SWZ256(o) ((o) ^ ((((o) >> 8) & 7) << 4))

__global__ __launch_bounds__(GT, 2) void gemm_kernel() {
    extern __shared__ char smem[];
    const uint32_t sb = smem_to_u32(smem);
    const int tid = threadIdx.x, wid = tid >> 5, lid = tid & 31;
    const int b = blockIdx.z, m0 = blockIdx.y * 128, n0 = blockIdx.x * 128;
    const int warp_m = wid & 3, warp_n = wid >> 2;

    const __half* Ap = g_Ah + (size_t)b * Cc * PTOT;
    const __half* Bp = g_Bt + (size_t)b * Cc * QPAD;

    float acc[2][8][4];
#pragma unroll
    for (int i = 0; i < 2; i++)
#pragma unroll
        for (int j = 0; j < 8; j++)
#pragma unroll
            for (int k = 0; k < 4; k++) acc[i][j][k] = 0.f;

    auto issue_loads = [&](int c, int buf) {
        int k_off = c * 64;
        uint32_t aB = sb + buf * BUF_B;
        uint32_t bB = aB + A_BYTES;
#pragma unroll
        for (int i = 0; i < 8; i++) {
            int idx = tid + i * GT;
            bool isB = idx >= 1024;
            int j = isB ? idx - 1024 : idx;
            int row = j >> 4, u = j & 15;
            const __half* src = isB
                ? Bp + (size_t)(k_off + row) * QPAD + n0 + u * 8
                : Ap + (size_t)(k_off + row) * PTOT + m0 + u * 8;
            uint32_t dst = (isB ? bB : aB) + row * 256 + ((u ^ (row & 7)) << 4);
            cp_async16(dst, src);
        }
        asm volatile("cp.async.commit_group;" ::: "memory");
    };

    issue_loads(0, 0);
    issue_loads(1, 1);

    const int krowA = ((lid >> 4) & 1) * 8 + (lid & 7);
    const int mbyteA = ((lid >> 3) & 1) * 16;
    const int krowB = ((lid >> 3) & 1) * 8 + (lid & 7);
    const int nbyteB = ((lid >> 4) & 1) * 16;

    for (int c = 0; c < 4; c++) {
        if (c < 3) asm volatile("cp.async.wait_group 1;" ::: "memory");
        else       asm volatile("cp.async.wait_group 0;" ::: "memory");
        __syncthreads();
        if (c < 2) issue_loads(c + 2, (c + 2) % 3);

        uint32_t aB = sb + (c % 3) * BUF_B;
        uint32_t bB = aB + A_BYTES;

#pragma unroll
        for (int ks = 0; ks < 4; ks++) {
            uint32_t af[2][4];
#pragma unroll
            for (int mb = 0; mb < 2; mb++) {
                uint32_t off = (uint32_t)((ks * 16 + krowA) * 256
                                          + warp_m * 64 + mb * 32 + mbyteA);
                ldsm_x4_trans(af[mb], aB + SWZ256(off));
            }
            uint32_t bf[4][4];
#pragma unroll
            for (int p = 0; p < 4; p++) {
                uint32_t off = (uint32_t)((ks * 16 + krowB) * 256
                                          + warp_n * 128 + p * 32 + nbyteB);
                ldsm_x4_trans(bf[p], bB + SWZ256(off));
            }
#pragma unroll
            for (int mb = 0; mb < 2; mb++)
#pragma unroll
                for (int nb = 0; nb < 8; nb++)
                    mma16816(acc[mb][nb], af[mb],
                             bf[nb >> 1][(nb & 1) * 2], bf[nb >> 1][(nb & 1) * 2 + 1]);
        }
    }

    const float scale = 0.0625f;
    const int rbase = m0 + warp_m * 32 + (lid >> 2);
    const int cbase = n0 + warp_n * 64 + (lid & 3) * 2;
#pragma unroll
    for (int mb = 0; mb < 2; mb++) {
#pragma unroll
        for (int nb = 0; nb < 8; nb++) {
            int q = cbase + nb * 8;
            if (q < QTOT) {
                int r0 = rbase + mb * 16;
                __half* c0p = g_corrh + ((size_t)b * PTOT + r0) * QTOT + q;
                __half* c1p = c0p + (size_t)8 * QTOT;
                *(__half2*)c0p = __floats2half2_rn(acc[mb][nb][0] * scale,
                                                   acc[mb][nb][1] * scale);
                *(__half2*)c1p = __floats2half2_rn(acc[mb][nb][2] * scale,
                                                   acc[mb][nb][3] * scale);
            }
        }
    }
}

// ---------------------------------------------------------------------------
// Kernel 3: sampler (round-14, unchanged). 256-thr block = 8 n-heads of one
// (b,h,w); overlapping half2 pairs; separable metadata. grid 8192.
// ---------------------------------------------------------------------------
#define PPITCH 20   // half2 units per pair row (80 B)
__global__ __launch_bounds__(256) void sample_kernel(const float* __restrict__ coords,
                                                     float* __restrict__ out) {
    const int warp = threadIdx.x >> 5;
    const int lane = threadIdx.x & 31;
    const int bhw = blockIdx.x;
    const int b = bhw >> 12;
    const int hw = bhw & 4095;
    const int h = hw >> 6;
    const int w = hw & 63;
    const int n = warp;
    const int qid = ((b * NN + n) << 12) | hw;

    __shared__ uint32_t pairs[8][4][10][PPITCH];
    __shared__ float2 xdat[8][4][9];
    __shared__ float2 ydat[8][4][9];

    const float cx = coords[((((size_t)b * NN + n) * 2 + 0) * HH + h) * WW + w];
    const float cy = coords[((((size_t)b * NN + n) * 2 + 1) * HH + h) * WW + w];

    const __half* corrRow = g_corrh + ((size_t)b * PTOT + hw) * QTOT;
    float* outBase = out + (size_t)qid * 324;

    const int   lvl_off[4] = {0, 4096, 5120, 5376};
    const int   wl[4]      = {64, 32, 16, 8};
    const float inv[4]     = {1.f, 0.5f, 0.25f, 0.125f};

#pragma unroll
    for (int lvl = 0; lvl < 4; lvl++) {
        const int   w2  = wl[lvl];
        const float wm1 = (float)(w2 - 1);
        const float cxs = cx * inv[lvl];
        const float cys = cy * inv[lvl];
        const float ylo = fminf(fmaxf(cys - 4.f, 0.f), wm1);
        const float yhi = fminf(fmaxf(cys + 4.f, 0.f), wm1);
        const float xlo = fminf(fmaxf(cxs - 4.f, 0.f), wm1);
        const int xstart = (int)floorf(xlo);
        const int ystart = (int)floorf(ylo);
        const int yend   = min((int)floorf(yhi) + 1, w2 - 1);
        const int xs4    = xstart & ~3;

        const __half* lbase = corrRow + lvl_off[lvl];
#pragma unroll
        for (int s = 0; s < 2; s++) {
            int slot = lane + s * 32;
            int r = slot >> 2, cb = slot & 3;
            int col = xs4 + cb * 4;
            uint2 v = make_uint2(0u, 0u);
            if (slot < 40 && r <= yend - ystart && col < w2)
                v = *(const uint2*)(lbase + (ystart + r) * w2 + col);
            uint32_t nxt = __shfl_down_sync(0xffffffffu, v.x, 1);
            uint32_t p0 = v.x;
            uint32_t p1 = (v.x >> 16) | (v.y << 16);
            uint32_t p2 = v.y;
            uint32_t p3 = (v.y >> 16) | (nxt << 16);
            if (slot < 40)
                *(uint4*)&pairs[warp][lvl][r][cb * 4] = make_uint4(p0, p1, p2, p3);
        }
        {
            int grp = lane >> 4;
            int off = lane & 15;
            if (off < 9 && grp < 2) {
                float c   = grp ? cys : cxs;
                int   sub = grp ? ystart : xs4;
                int   str = grp ? (PPITCH * 4) : 4;
                int   bas = grp ? (warp * 4 + lvl) * (10 * PPITCH * 4) : 0;
                float v   = fminf(fmaxf(c + (float)(off - 4), 0.f), wm1);
                float v0f = floorf(v);
                float f   = v - v0f;
                int   i0  = (int)v0f;
                uint32_t packed;
                if (grp) {
                    int i1 = min(i0 + 1, w2 - 1);
                    packed = (uint32_t)(bas + (i0 - sub) * str)
                           | ((uint32_t)(bas + (i1 - sub) * str) << 16);
                } else {
                    packed = (uint32_t)((i0 - sub) * str);
                }
                float2 md = make_float2(f, __uint_as_float(packed));
                if (grp) ydat[warp][lvl][off] = md;
                else     xdat[warp][lvl][off] = md;
            }
        }
    }
    __syncwarp();

    const char* pbase = (const char*)&pairs[0][0][0][0];
#pragma unroll
    for (int s = 0; s < 3; s++) {
        int t = lane + s * 32;
        if (t < 81) {
            int ix = t / 9;
            int iy = t - ix * 9;
#pragma unroll
            for (int lvl = 0; lvl < 4; lvl++) {
                float2 xd = xdat[warp][lvl][ix];
                float2 yd = ydat[warp][lvl][iy];
                uint32_t xo = __float_as_uint(xd.y);
                uint32_t yp = __float_as_uint(yd.y);
                uint32_t pa = *(const uint32_t*)(pbase + (yp & 0xFFFFu) + xo);
                uint32_t pc = *(const uint32_t*)(pbase + (yp >> 16) + xo);
                float2 a = __half22float2(*(__half2*)&pa);
                float2 c2 = __half22float2(*(__half2*)&pc);
                float h0 = fmaf(xd.x, a.y - a.x, a.x);
                float h1 = fmaf(xd.x, c2.y - c2.x, c2.x);
                outBase[lvl * 81 + t] = fmaf(yd.x, h1 - h0, h0);
            }
        }
    }
}

// ---------------------------------------------------------------------------
// Launch
// ---------------------------------------------------------------------------
extern "C" void kernel_launch(void* const* d_in, const int* in_sizes, int n_in,
                              void* d_out, int out_size) {
    const float* f1     = (const float*)d_in[0];
    const float* f2     = (const float*)d_in[1];
    const float* coords = (const float*)d_in[2];
    float* out          = (float*)d_out;

    prep_kernel<<<512 + 1024, 256>>>(f2, f1);

    cudaFuncSetAttribute(gemm_kernel, cudaFuncAttributeMaxDynamicSharedMemorySize, GEMM_SMEM);
    gemm_kernel<<<dim3(NTILES, PTOT / 128, Bb), GT, GEMM_SMEM>>>();

    sample_kernel<<<Bb * HH * WW, 256>>>(coords, out);
}

// round 17
// speedup vs baseline: 1.0477x; 1.0319x over previous
#include <cuda_runtime.h>
#include <cuda_fp16.h>
#include <cstdint>

// ---------------------------------------------------------------------------
// CorrBlock: pooled-fmap2 fp16 HMMA GEMM (1-pass: Ahi*Bhi) + warp sampler.
// Round 17: sampler phase-1 gathers via predicated 8B cp.async.ca (deletes the
//   LDG->shfl->PRMT->STS pair-building chain); phase 2 reads raw fp16 patch
//   (4 LDS.U16 per output — pairs trick measured neutral in round 14).
// GEMM (round-16, NTILES=43) and prep (round-14 shape) frozen at optima.
// ---------------------------------------------------------------------------

#define Bb 2
#define Cc 256
#define HH 64
#define WW 64
#define NN 8
#define QTOT 5440
#define QPAD 5632      // stride; pad region = don't-care
#define PTOT 4096      // H*W
#define NTILES 43      // ceil(5440/128); 44th tile entirely q>=5504 waste

// Scratch (no cudaMalloc allowed)
__device__ __half g_Bt[(size_t)Bb * Cc * QPAD];           // 5.8 MB [b][c][QPAD] fp16
__device__ __half g_Ah[(size_t)Bb * Cc * PTOT];           // 4.2 MB [b][c][m] fp16
__device__ __half g_corrh[(size_t)Bb * PTOT * QTOT];      // 89 MB  fp16 corr

__device__ __forceinline__ uint32_t smem_to_u32(const void* p) {
    uint32_t a;
    asm("{ .reg .u64 t; cvta.to.shared.u64 t, %1; cvt.u32.u64 %0, t; }" : "=r"(a) : "l"(p));
    return a;
}
__device__ __forceinline__ void cp_async16(uint32_t dst, const void* src) {
    asm volatile("cp.async.cg.shared.global [%0], [%1], 16;" :: "r"(dst), "l"(src));
}
__device__ __forceinline__ void cp_async8(uint32_t dst, const void* src) {
    asm volatile("cp.async.ca.shared.global [%0], [%1], 8;" :: "r"(dst), "l"(src));
}
__device__ __forceinline__ void ldsm_x4_trans(uint32_t* r, uint32_t addr) {
    asm volatile("ldmatrix.sync.aligned.m8n8.x4.trans.shared.b16 {%0,%1,%2,%3}, [%4];"
                 : "=r"(r[0]), "=r"(r[1]), "=r"(r[2]), "=r"(r[3]) : "r"(addr));
}
__device__ __forceinline__ void mma16816(float* d, const uint32_t* a, uint32_t b0, uint32_t b1) {
    asm volatile("mma.sync.aligned.m16n8k16.row.col.f32.f16.f16.f32 "
                 "{%0,%1,%2,%3}, {%4,%5,%6,%7}, {%8,%9}, {%0,%1,%2,%3};"
                 : "+f"(d[0]), "+f"(d[1]), "+f"(d[2]), "+f"(d[3])
                 : "r"(a[0]), "r"(a[1]), "r"(a[2]), "r"(a[3]), "r"(b0), "r"(b1));
}

// ---------------------------------------------------------------------------
// Kernel 1: fused prep (round-14 shape). Blocks [0,512): pool fmap2 -> g_Bt.
//           Blocks [512,1536): fp32->fp16 copy of f1 (2 float4/thread).
// ---------------------------------------------------------------------------
__global__ __launch_bounds__(256) void prep_kernel(const float* __restrict__ f2,
                                                   const float* __restrict__ f1) {
    __shared__ float s0[4096];
    __shared__ float s1[1024];
    __shared__ float s2[256];
    const int blk = blockIdx.x;
    const int tid = threadIdx.x;

    if (blk < 512) {
        int c = blk & 255, b = blk >> 8;
        const float* in = f2 + ((size_t)b * Cc + c) * (HH * WW);
        __half* outp = g_Bt + ((size_t)b * Cc + c) * QPAD;
        for (int i = tid; i < 1024; i += 256) {
            float4 v = ((const float4*)in)[i];
            ((float4*)s0)[i] = v;
            ((__half2*)outp)[2 * i]     = __floats2half2_rn(v.x, v.y);
            ((__half2*)outp)[2 * i + 1] = __floats2half2_rn(v.z, v.w);
        }
        __syncthreads();
        for (int o = tid; o < 1024; o += 256) {
            int y = o >> 5, x = o & 31;
            float v = 0.25f * (s0[(2*y)*64 + 2*x] + s0[(2*y)*64 + 2*x + 1]
                             + s0[(2*y+1)*64 + 2*x] + s0[(2*y+1)*64 + 2*x + 1]);
            s1[o] = v; outp[4096 + o] = __float2half_rn(v);
        }
        __syncthreads();
        {
            int y = tid >> 4, x = tid & 15;
            float v = 0.25f * (s1[(2*y)*32 + 2*x] + s1[(2*y)*32 + 2*x + 1]
                             + s1[(2*y+1)*32 + 2*x] + s1[(2*y+1)*32 + 2*x + 1]);
            s2[tid] = v; outp[5120 + tid] = __float2half_rn(v);
        }
        __syncthreads();
        if (tid < 64) {
            int y = tid >> 3, x = tid & 7;
            float v = 0.25f * (s2[(2*y)*16 + 2*x] + s2[(2*y)*16 + 2*x + 1]
                             + s2[(2*y+1)*16 + 2*x] + s2[(2*y+1)*16 + 2*x + 1]);
            outp[5376 + tid] = __float2half_rn(v);
        }
    } else {
        int blk2 = blk - 512;                    // 0..1023
        size_t base = (size_t)blk2 * 512 + tid * 2;   // float4 units
#pragma unroll
        for (int i = 0; i < 2; i++) {
            float4 v = ((const float4*)f1)[base + i];
            ((__half2*)g_Ah)[(base + i) * 2]     = __floats2half2_rn(v.x, v.y);
            ((__half2*)g_Ah)[(base + i) * 2 + 1] = __floats2half2_rn(v.z, v.w);
        }
    }
}

// ---------------------------------------------------------------------------
// Kernel 2: HMMA GEMM (round-16, unchanged). CTA 128x128, BK=64, 4 chunks,
// 256 thr / 8 warps (32x64), 3-stage cp.async, 2 CTAs/SM, trans-ldsm operands.
// grid (43, 32, 2).
// ---------------------------------------------------------------------------
#define GT 256
static constexpr int A_BYTES = 64 * 256;
static constexpr int B_BYTES = 64 * 256;
static constexpr int BUF_B = A_BYTES + B_BYTES;  // 32 KB
static constexpr int GEMM_SMEM = 3 * BUF_B;      // 96 KB
#define SWZ256(o) ((o) ^ ((((o) >> 8) & 7) << 4))

__global__ __launch_bounds__(GT, 2) void gemm_kernel() {
    extern __shared__ char smem[];
    const uint32_t sb = smem_to_u32(smem);
    const int tid = threadIdx.x, wid = tid >> 5, lid = tid & 31;
    const int b = blockIdx.z, m0 = blockIdx.y * 128, n0 = blockIdx.x * 128;
    const int warp_m = wid & 3, warp_n = wid >> 2;

    const __half* Ap = g_Ah + (size_t)b * Cc * PTOT;
    const __half* Bp = g_Bt + (size_t)b * Cc * QPAD;

    float acc[2][8][4];
#pragma unroll
    for (int i = 0; i < 2; i++)
#pragma unroll
        for (int j = 0; j < 8; j++)
#pragma unroll
            for (int k = 0; k < 4; k++) acc[i][j][k] = 0.f;

    auto issue_loads = [&](int c, int buf) {
        int k_off = c * 64;
        uint32_t aB = sb + buf * BUF_B;
        uint32_t bB = aB + A_BYTES;
#pragma unroll
        for (int i = 0; i < 8; i++) {
            int idx = tid + i * GT;
            bool isB = idx >= 1024;
            int j = isB ? idx - 1024 : idx;
            int row = j >> 4, u = j & 15;
            const __half* src = isB
                ? Bp + (size_t)(k_off + row) * QPAD + n0 + u * 8
                : Ap + (size_t)(k_off + row) * PTOT + m0 + u * 8;
            uint32_t dst = (isB ? bB : aB) + row * 256 + ((u ^ (row & 7)) << 4);
            cp_async16(dst, src);
        }
        asm volatile("cp.async.commit_group;" ::: "memory");
    };

    issue_loads(0, 0);
    issue_loads(1, 1);

    const int krowA = ((lid >> 4) & 1) * 8 + (lid & 7);
    const int mbyteA = ((lid >> 3) & 1) * 16;
    const int krowB = ((lid >> 3) & 1) * 8 + (lid & 7);
    const int nbyteB = ((lid >> 4) & 1) * 16;

    for (int c = 0; c < 4; c++) {
        if (c < 3) asm volatile("cp.async.wait_group 1;" ::: "memory");
        else       asm volatile("cp.async.wait_group 0;" ::: "memory");
        __syncthreads();
        if (c < 2) issue_loads(c + 2, (c + 2) % 3);

        uint32_t aB = sb + (c % 3) * BUF_B;
        uint32_t bB = aB + A_BYTES;

#pragma unroll
        for (int ks = 0; ks < 4; ks++) {
            uint32_t af[2][4];
#pragma unroll
            for (int mb = 0; mb < 2; mb++) {
                uint32_t off = (uint32_t)((ks * 16 + krowA) * 256
                                          + warp_m * 64 + mb * 32 + mbyteA);
                ldsm_x4_trans(af[mb], aB + SWZ256(off));
            }
            uint32_t bf[4][4];
#pragma unroll
            for (int p = 0; p < 4; p++) {
                uint32_t off = (uint32_t)((ks * 16 + krowB) * 256
                                          + warp_n * 128 + p * 32 + nbyteB);
                ldsm_x4_trans(bf[p], bB + SWZ256(off));
            }
#pragma unroll
            for (int mb = 0; mb < 2; mb++)
#pragma unroll
                for (int nb = 0; nb < 8; nb++)
                    mma16816(acc[mb][nb], af[mb],
                             bf[nb >> 1][(nb & 1) * 2], bf[nb >> 1][(nb & 1) * 2 + 1]);
        }
    }

    const float scale = 0.0625f;
    const int rbase = m0 + warp_m * 32 + (lid >> 2);
    const int cbase = n0 + warp_n * 64 + (lid & 3) * 2;
#pragma unroll
    for (int mb = 0; mb < 2; mb++) {
#pragma unroll
        for (int nb = 0; nb < 8; nb++) {
            int q = cbase + nb * 8;
            if (q < QTOT) {
                int r0 = rbase + mb * 16;
                __half* c0p = g_corrh + ((size_t)b * PTOT + r0) * QTOT + q;
                __half* c1p = c0p + (size_t)8 * QTOT;
                *(__half2*)c0p = __floats2half2_rn(acc[mb][nb][0] * scale,
                                                   acc[mb][nb][1] * scale);
                *(__half2*)c1p = __floats2half2_rn(acc[mb][nb][2] * scale,
                                                   acc[mb][nb][3] * scale);
            }
        }
    }
}

// ---------------------------------------------------------------------------
// Kernel 3: sampler. 256-thr block = 8 warps = 8 n-heads of one (b,h,w).
// Phase 1: predicated 8B cp.async gathers into raw fp16 patch (rows padded to
// 24 halves = 48 B: 8B-aligned dst, 12-bank row spread) + separable metadata.
// Phase 2: 4 LDS.U16 corner reads + 6-op bilinear. grid 8192.
// ---------------------------------------------------------------------------
#define PPITCH 24   // halves per patch row (48 B)
__global__ __launch_bounds__(256) void sample_kernel(const float* __restrict__ coords,
                                                     float* __restrict__ out) {
    const int warp = threadIdx.x >> 5;
    const int lane = threadIdx.x & 31;
    const int bhw = blockIdx.x;
    const int b = bhw >> 12;
    const int hw = bhw & 4095;
    const int h = hw >> 6;
    const int w = hw & 63;
    const int n = warp;
    const int qid = ((b * NN + n) << 12) | hw;

    __shared__ __half patch[8][4][10][PPITCH];  // raw fp16 patch
    __shared__ float2 xdat[8][4][9];            // {fx, x0*2 | x1*2 <<16} (bytes)
    __shared__ float2 ydat[8][4][9];            // {fy, abs y0 | abs y1 <<16}

    const float cx = coords[((((size_t)b * NN + n) * 2 + 0) * HH + h) * WW + w];
    const float cy = coords[((((size_t)b * NN + n) * 2 + 1) * HH + h) * WW + w];

    const __half* corrRow = g_corrh + ((size_t)b * PTOT + hw) * QTOT;
    float* outBase = out + (size_t)qid * 324;

    const int   lvl_off[4] = {0, 4096, 5120, 5376};
    const int   wl[4]      = {64, 32, 16, 8};
    const float inv[4]     = {1.f, 0.5f, 0.25f, 0.125f};

    const uint32_t patch_base = smem_to_u32(&patch[warp][0][0][0]);

    // Phase 1: predicated cp.async gathers + separable metadata
#pragma unroll
    for (int lvl = 0; lvl < 4; lvl++) {
        const int   w2  = wl[lvl];
        const float wm1 = (float)(w2 - 1);
        const float cxs = cx * inv[lvl];
        const float cys = cy * inv[lvl];
        const float ylo = fminf(fmaxf(cys - 4.f, 0.f), wm1);
        const float yhi = fminf(fmaxf(cys + 4.f, 0.f), wm1);
        const float xlo = fminf(fmaxf(cxs - 4.f, 0.f), wm1);
        const int xstart = (int)floorf(xlo);
        const int ystart = (int)floorf(ylo);
        const int yend   = min((int)floorf(yhi) + 1, w2 - 1);
        const int xs4    = xstart & ~3;

        const __half* lbase = corrRow + lvl_off[lvl];
#pragma unroll
        for (int s = 0; s < 2; s++) {
            int slot = lane + s * 32;
            int r = slot >> 2, cb = slot & 3;
            int col = xs4 + cb * 4;
            if (slot < 40 && r <= yend - ystart && col < w2) {
                cp_async8(patch_base + (lvl * 10 + r) * (PPITCH * 2) + cb * 8,
                          lbase + (ystart + r) * w2 + col);
            }
        }
        // metadata: lanes 0-8 -> x (relative bytes), 16-24 -> y (absolute)
        {
            int grp = lane >> 4;
            int off = lane & 15;
            if (off < 9 && grp < 2) {
                float c   = grp ? cys : cxs;
                int   sub = grp ? ystart : xs4;
                int   str = grp ? (PPITCH * 2) : 2;
                int   bas = grp ? (warp * 4 + lvl) * (10 * PPITCH * 2) : 0;
                float v   = fminf(fmaxf(c + (float)(off - 4), 0.f), wm1);
                float v0f = floorf(v);
                float f   = v - v0f;
                int   i0  = (int)v0f;
                int   i1  = min(i0 + 1, w2 - 1);
                uint32_t packed = (uint32_t)(bas + (i0 - sub) * str)
                                | ((uint32_t)(bas + (i1 - sub) * str) << 16);
                float2 md = make_float2(f, __uint_as_float(packed));
                if (grp) ydat[warp][lvl][off] = md;
                else     xdat[warp][lvl][off] = md;
            }
        }
    }
    asm volatile("cp.async.commit_group;" ::: "memory");
    asm volatile("cp.async.wait_group 0;" ::: "memory");
    __syncwarp();

    // Phase 2: table-driven separable bilinear (clamped indices only touch
    // written slots)
    const char* pbase = (const char*)&patch[0][0][0][0];
#pragma unroll
    for (int s = 0; s < 3; s++) {
        int t = lane + s * 32;
        if (t < 81) {
            int ix = t / 9;
            int iy = t - ix * 9;
#pragma unroll
            for (int lvl = 0; lvl < 4; lvl++) {
                float2 xd = xdat[warp][lvl][ix];
                float2 yd = ydat[warp][lvl][iy];
                uint32_t xp = __float_as_uint(xd.y);
                uint32_t yp = __float_as_uint(yd.y);
                uint32_t y0o = yp & 0xFFFFu, y1o = yp >> 16;
                uint32_t x0o = xp & 0xFFFFu, x1o = xp >> 16;
                float v00 = __half2float(*(const __half*)(pbase + y0o + x0o));
                float v01 = __half2float(*(const __half*)(pbase + y0o + x1o));
                float v10 = __half2float(*(const __half*)(pbase + y1o + x0o));
                float v11 = __half2float(*(const __half*)(pbase + y1o + x1o));
                float h0 = fmaf(xd.x, v01 - v00, v00);
                float h1 = fmaf(xd.x, v11 - v10, v10);
                outBase[lvl * 81 + t] = fmaf(yd.x, h1 - h0, h0);
            }
        }
    }
}

// ---------------------------------------------------------------------------
// Launch
// ---------------------------------------------------------------------------
extern "C" void kernel_launch(void* const* d_in, const int* in_sizes, int n_in,
                              void* d_out, int out_size) {
    const float* f1     = (const float*)d_in[0];
    const float* f2     = (const float*)d_in[1];
    const float* coords = (const float*)d_in[2];
    float* out          = (float*)d_out;

    prep_kernel<<<512 + 1024, 256>>>(f2, f1);

    cudaFuncSetAttribute(gemm_kernel, cudaFuncAttributeMaxDynamicSharedMemorySize, GEMM_SMEM);
    gemm_kernel<<<dim3(NTILES, PTOT / 128, Bb), GT, GEMM_SMEM>>>();

    sample_kernel<<<Bb * HH * WW, 256>>>(coords, out);
}